// round 2
// baseline (speedup 1.0000x reference)
#include <cuda_runtime.h>
#include <math.h>

#define BB 8
#define NN 2048
#define FF 64
#define TI 128
#define TJ 64

typedef unsigned long long u64;

// Scratch (allocation-free rule: device globals)
__device__ __align__(16) float g_h[BB * NN * FF];
__device__ __align__(16) float g_f1[BB * NN];
__device__ __align__(16) float g_f2[BB * NN];

#define FMA2(d, a, b, c) \
    asm("fma.rn.f32x2 %0,%1,%2,%3;" : "=l"(d) : "l"(a), "l"(b), "l"(c))
#define UNPACK2(lo, hi, s) \
    asm("mov.b64 {%0,%1},%2;" : "=f"(lo), "=f"(hi) : "l"(s))

// ---------------------------------------------------------------------------
// Kernel 1: h = inp@W fused with f1 = h@a1, f2 = h@a2.
// 128 CTAs x 256 threads. CTA tile: 128 rows x 64 cols, thread tile 4r x 8c.
// inp staged transposed + duplicated (f32x2 broadcast operand), W natural.
// ---------------------------------------------------------------------------
#define PR2 130  // IsT2 row stride in float2 (1040B: 16B-aligned, bank-skewed)
#define KHF_SMEM (FF * FF * 4 + FF * PR2 * 8)

__global__ void __launch_bounds__(256) k_hf(const float* __restrict__ inp,
                                            const float* __restrict__ W,
                                            const float* __restrict__ a) {
    extern __shared__ char smem[];
    float*  Ws   = (float*)smem;                 // [k][c] 16KB
    float2* IsT2 = (float2*)(smem + FF * FF * 4);  // [k][r] dup, 66.5KB

    const int t    = threadIdx.x;
    const int row0 = blockIdx.x * TI;
    const int tx   = t & 7;    // col group: cols tx*8 .. tx*8+7
    const int ty   = t >> 3;   // row group: rows ty*4 .. ty*4+3

#pragma unroll
    for (int q = 0; q < 4; ++q)
        ((float4*)Ws)[t + 256 * q] = ((const float4*)W)[t + 256 * q];

#pragma unroll
    for (int q = 0; q < 8; ++q) {
        int idx = t + 256 * q;          // 2048 float4 in the 128x64 tile
        int r = idx >> 4, k4 = (idx & 15) * 4;
        float4 v = ((const float4*)(inp + (size_t)(row0 + r) * FF))[idx & 15];
        IsT2[(k4 + 0) * PR2 + r] = make_float2(v.x, v.x);
        IsT2[(k4 + 1) * PR2 + r] = make_float2(v.y, v.y);
        IsT2[(k4 + 2) * PR2 + r] = make_float2(v.z, v.z);
        IsT2[(k4 + 3) * PR2 + r] = make_float2(v.w, v.w);
    }
    __syncthreads();

    u64 acc[4][4] = {};
#pragma unroll 8
    for (int k = 0; k < FF; ++k) {
        ulonglong2 p0 = *(const ulonglong2*)&IsT2[k * PR2 + ty * 4];
        ulonglong2 p1 = *(const ulonglong2*)&IsT2[k * PR2 + ty * 4 + 2];
        u64 pd[4] = {p0.x, p0.y, p1.x, p1.y};
        ulonglong2 h0 = *(const ulonglong2*)&Ws[k * FF + tx * 8];
        ulonglong2 h1 = *(const ulonglong2*)&Ws[k * FF + tx * 8 + 4];
        u64 hp[4] = {h0.x, h0.y, h1.x, h1.y};
#pragma unroll
        for (int r = 0; r < 4; ++r)
#pragma unroll
            for (int c = 0; c < 4; ++c) FMA2(acc[r][c], pd[r], hp[c], acc[r][c]);
    }

    float av1[8], av2[8];
#pragma unroll
    for (int c = 0; c < 8; ++c) {
        av1[c] = __ldg(a + tx * 8 + c);
        av2[c] = __ldg(a + 64 + tx * 8 + c);
    }
#pragma unroll
    for (int r = 0; r < 4; ++r) {
        const int row = row0 + ty * 4 + r;
        float hr[8];
#pragma unroll
        for (int c = 0; c < 4; ++c) UNPACK2(hr[2 * c], hr[2 * c + 1], acc[r][c]);
        float4* dst = (float4*)(g_h + (size_t)row * FF + tx * 8);
        dst[0] = make_float4(hr[0], hr[1], hr[2], hr[3]);
        dst[1] = make_float4(hr[4], hr[5], hr[6], hr[7]);
        float s1 = 0.f, s2 = 0.f;
#pragma unroll
        for (int c = 0; c < 8; ++c) { s1 += hr[c] * av1[c]; s2 += hr[c] * av2[c]; }
#pragma unroll
        for (int o = 1; o < 8; o <<= 1) {
            s1 += __shfl_xor_sync(0xffffffffu, s1, o);
            s2 += __shfl_xor_sync(0xffffffffu, s2, o);
        }
        if (tx == 0) { g_f1[row] = s1; g_f2[row] = s2; }
    }
}

// ---------------------------------------------------------------------------
// Kernel 2: fused masked attention + P@h + ELU.
// No online max (scores bounded: |f1+f2| <~ 12, exp safe in fp32).
// grid = (N/TI=16, B=8) = 128 CTAs x 256 threads, CTA tile 128 rows.
// Per j-tile of 64: scores -> pT2 (p duplicated {p,p}), then f32x2 GEMM.
// adj + h tiles register-prefetched one tile ahead.
// ---------------------------------------------------------------------------
#define PRA 128  // pT2 row stride in float2 (1KB rows)
#define ATTN_SMEM (TJ * FF * 4 + TJ * PRA * 8 + 2 * TI * 4)

__global__ void __launch_bounds__(256) k_attn(const int* __restrict__ adj,
                                              float* __restrict__ out) {
    extern __shared__ char smem[];
    float*  h_s = (float*)smem;                        // [k][c] 16KB
    float2* pT2 = (float2*)(smem + TJ * FF * 4);       // [j][r] dup, 64KB
    float*  Sp  = (float*)(smem + TJ * FF * 4 + TJ * PRA * 8);  // [2][TI]

    const int t  = threadIdx.x;
    const int b  = blockIdx.y;
    const int i0 = blockIdx.x * TI;
    // score identity: warps 0-3 take j-half 0, warps 4-7 take j-half 1
    const int sr   = t & 127;
    const int jh   = (t >> 7) * 32;
    const int lane = t & 31;
    // gemm identity
    const int tx = t & 7;
    const int ty = t >> 3;

    const float* hb   = g_h + (size_t)b * NN * FF;
    const int*   arow = adj + ((size_t)b * NN + i0 + sr) * NN;
    const float  f1v  = g_f1[b * NN + i0 + sr];
    const float* f2b  = g_f2 + b * NN;

    // prefetch tile 0
    int4 av[8];
    float4 hv[4];
#pragma unroll
    for (int u = 0; u < 8; ++u) av[u] = ((const int4*)(arow + jh))[u];
#pragma unroll
    for (int q = 0; q < 4; ++q) hv[q] = ((const float4*)hb)[t + 256 * q];

    float Sacc = 0.f;
    u64 acc[4][4] = {};

    for (int j0 = 0; j0 < NN; j0 += TJ) {
        __syncthreads();  // previous GEMM finished reading smem

        // stage h tile
#pragma unroll
        for (int q = 0; q < 4; ++q) ((float4*)h_s)[t + 256 * q] = hv[q];

        // scores for 32 j's of row sr
        {
            const float f2l = f2b[j0 + jh + lane];
            const int* ai = (const int*)av;
#pragma unroll
            for (int u = 0; u < 32; ++u) {
                float f2u = __shfl_sync(0xffffffffu, f2l, u);
                float x = f1v + f2u;
                x = fmaxf(x, 0.2f * x);                 // leaky relu (slope<1)
                float e = __expf(x);
                float p = (ai[u] > 0) ? e : 0.f;
                Sacc += p;
                pT2[(jh + u) * PRA + sr] = make_float2(p, p);
            }
        }

        // prefetch next tile (hidden under GEMM)
        const int jn = j0 + TJ;
        if (jn < NN) {
#pragma unroll
            for (int u = 0; u < 8; ++u) av[u] = ((const int4*)(arow + jn + jh))[u];
#pragma unroll
            for (int q = 0; q < 4; ++q)
                hv[q] = ((const float4*)(hb + (size_t)jn * FF))[t + 256 * q];
        }
        __syncthreads();

        // 128x64x64 GEMM accumulate, f32x2
#pragma unroll 8
        for (int k = 0; k < TJ; ++k) {
            ulonglong2 p0 = *(const ulonglong2*)&pT2[k * PRA + ty * 4];
            ulonglong2 p1 = *(const ulonglong2*)&pT2[k * PRA + ty * 4 + 2];
            u64 pd[4] = {p0.x, p0.y, p1.x, p1.y};
            ulonglong2 h0 = *(const ulonglong2*)&h_s[k * FF + tx * 8];
            ulonglong2 h1 = *(const ulonglong2*)&h_s[k * FF + tx * 8 + 4];
            u64 hp[4] = {h0.x, h0.y, h1.x, h1.y};
#pragma unroll
            for (int r = 0; r < 4; ++r)
#pragma unroll
                for (int c = 0; c < 4; ++c) FMA2(acc[r][c], pd[r], hp[c], acc[r][c]);
        }
    }

    __syncthreads();
    Sp[(t >> 7) * TI + sr] = Sacc;
    __syncthreads();

#pragma unroll
    for (int r = 0; r < 4; ++r) {
        const int row = ty * 4 + r;
        const float inv = 1.0f / (Sp[row] + Sp[TI + row]);
        float o[8];
#pragma unroll
        for (int c = 0; c < 4; ++c) {
            float lo, hi;
            UNPACK2(lo, hi, acc[r][c]);
            o[2 * c] = lo * inv;
            o[2 * c + 1] = hi * inv;
        }
#pragma unroll
        for (int c = 0; c < 8; ++c) o[c] = o[c] > 0.f ? o[c] : expm1f(o[c]);
        float4* dst = (float4*)(out + ((size_t)b * NN + i0 + row) * FF + tx * 8);
        dst[0] = make_float4(o[0], o[1], o[2], o[3]);
        dst[1] = make_float4(o[4], o[5], o[6], o[7]);
    }
}

// ---------------------------------------------------------------------------
extern "C" void kernel_launch(void* const* d_in, const int* in_sizes, int n_in,
                              void* d_out, int out_size) {
    const float* inp = (const float*)d_in[0];
    const int*   adj = (const int*)d_in[1];
    const float* W   = (const float*)d_in[2];
    const float* a   = (const float*)d_in[3];
    float* out = (float*)d_out;

    cudaFuncSetAttribute(k_hf, cudaFuncAttributeMaxDynamicSharedMemorySize, KHF_SMEM);
    cudaFuncSetAttribute(k_attn, cudaFuncAttributeMaxDynamicSharedMemorySize, ATTN_SMEM);

    k_hf<<<(BB * NN) / TI, 256, KHF_SMEM>>>(inp, W, a);
    dim3 g(NN / TI, BB);
    k_attn<<<g, 256, ATTN_SMEM>>>(adj, out);
}

// round 3
// speedup vs baseline: 1.1217x; 1.1217x over previous
#include <cuda_runtime.h>
#include <math.h>

#define BB 8
#define NN 2048
#define FF 64
#define TJ 64
#define PTS 68   // pT row stride: 272B (16B-aligned), 4-way STS conflict accepted

typedef unsigned long long u64;

__device__ __align__(16) float g_h[BB * NN * FF];
__device__ __align__(16) float g_f1[BB * NN];
__device__ __align__(16) float g_f2[BB * NN];

#define FMA2(d, a, b, c) \
    asm("fma.rn.f32x2 %0,%1,%2,%3;" : "=l"(d) : "l"(a), "l"(b), "l"(c))
#define UNPACK2(lo, hi, s) \
    asm("mov.b64 {%0,%1},%2;" : "=f"(lo), "=f"(hi) : "l"(s))
#define PACKDUP(d, x) \
    asm("mov.b64 %0,{%1,%1};" : "=l"(d) : "f"(x))

// ---------------------------------------------------------------------------
// Kernel 1 (known good from R2, ~6us): h = inp@W fused with f1/f2.
// ---------------------------------------------------------------------------
#define PR2 130
#define KHF_SMEM (FF * FF * 4 + FF * PR2 * 8)

__global__ void __launch_bounds__(256) k_hf(const float* __restrict__ inp,
                                            const float* __restrict__ W,
                                            const float* __restrict__ a) {
    extern __shared__ char smem[];
    float*  Ws   = (float*)smem;
    float2* IsT2 = (float2*)(smem + FF * FF * 4);

    const int t    = threadIdx.x;
    const int row0 = blockIdx.x * 128;
    const int tx   = t & 7;
    const int ty   = t >> 3;

#pragma unroll
    for (int q = 0; q < 4; ++q)
        ((float4*)Ws)[t + 256 * q] = ((const float4*)W)[t + 256 * q];

#pragma unroll
    for (int q = 0; q < 8; ++q) {
        int idx = t + 256 * q;
        int r = idx >> 4, k4 = (idx & 15) * 4;
        float4 v = ((const float4*)(inp + (size_t)(row0 + r) * FF))[idx & 15];
        IsT2[(k4 + 0) * PR2 + r] = make_float2(v.x, v.x);
        IsT2[(k4 + 1) * PR2 + r] = make_float2(v.y, v.y);
        IsT2[(k4 + 2) * PR2 + r] = make_float2(v.z, v.z);
        IsT2[(k4 + 3) * PR2 + r] = make_float2(v.w, v.w);
    }
    __syncthreads();

    u64 acc[4][4] = {};
#pragma unroll 8
    for (int k = 0; k < FF; ++k) {
        ulonglong2 p0 = *(const ulonglong2*)&IsT2[k * PR2 + ty * 4];
        ulonglong2 p1 = *(const ulonglong2*)&IsT2[k * PR2 + ty * 4 + 2];
        u64 pd[4] = {p0.x, p0.y, p1.x, p1.y};
        ulonglong2 h0 = *(const ulonglong2*)&Ws[k * FF + tx * 8];
        ulonglong2 h1 = *(const ulonglong2*)&Ws[k * FF + tx * 8 + 4];
        u64 hp[4] = {h0.x, h0.y, h1.x, h1.y};
#pragma unroll
        for (int r = 0; r < 4; ++r)
#pragma unroll
            for (int c = 0; c < 4; ++c) FMA2(acc[r][c], pd[r], hp[c], acc[r][c]);
    }

    float av1[8], av2[8];
#pragma unroll
    for (int c = 0; c < 8; ++c) {
        av1[c] = __ldg(a + tx * 8 + c);
        av2[c] = __ldg(a + 64 + tx * 8 + c);
    }
#pragma unroll
    for (int r = 0; r < 4; ++r) {
        const int row = row0 + ty * 4 + r;
        float hr[8];
#pragma unroll
        for (int c = 0; c < 4; ++c) UNPACK2(hr[2 * c], hr[2 * c + 1], acc[r][c]);
        float4* dst = (float4*)(g_h + (size_t)row * FF + tx * 8);
        dst[0] = make_float4(hr[0], hr[1], hr[2], hr[3]);
        dst[1] = make_float4(hr[4], hr[5], hr[6], hr[7]);
        float s1 = 0.f, s2 = 0.f;
#pragma unroll
        for (int c = 0; c < 8; ++c) { s1 += hr[c] * av1[c]; s2 += hr[c] * av2[c]; }
#pragma unroll
        for (int o = 1; o < 8; o <<= 1) {
            s1 += __shfl_xor_sync(0xffffffffu, s1, o);
            s2 += __shfl_xor_sync(0xffffffffu, s2, o);
        }
        if (tx == 0) { g_f1[row] = s1; g_f2[row] = s2; }
    }
}

// ---------------------------------------------------------------------------
// Kernel 2: fused masked attention + P@h + ELU.
// 256 CTAs x 128 threads (TI=64 rows each), j-tiles of 64.
// Score phase: warp w owns rows 16w..16w+15; lane = j column (coalesced adj).
// GEMM phase: 16x8 threads, 4r x 8c tile, f32x2 FMA; p packed on the fly.
// ---------------------------------------------------------------------------
#define ATTN_SMEM 0

__global__ void __launch_bounds__(128, 4) k_attn(const int* __restrict__ adj,
                                                 float* __restrict__ out) {
    __shared__ float h_s[TJ * FF];     // [k][c] 16KB
    __shared__ float pT[TJ * PTS];     // [j][r] 17.4KB
    __shared__ float Srow[64];

    const int t    = threadIdx.x;
    const int w    = t >> 5;
    const int lane = t & 31;
    const int b    = blockIdx.y;
    const int i0   = blockIdx.x * 64;
    // gemm identity
    const int tx = t & 7;
    const int ty = t >> 3;

    const float* hb   = g_h + (size_t)b * NN * FF;
    const float* f2b  = g_f2 + (size_t)b * NN;
    const int*   arow = adj + ((size_t)b * NN + i0 + 16 * w) * NN + lane;

    // f1 for this warp's 16 rows (broadcast loads, L2-resident)
    float f1r[16];
#pragma unroll
    for (int q = 0; q < 16; ++q) f1r[q] = __ldg(g_f1 + b * NN + i0 + 16 * w + q);

    float Sacc[16];
#pragma unroll
    for (int q = 0; q < 16; ++q) Sacc[q] = 0.f;
    u64 acc[4][4] = {};

    const float L2E = 1.44269504089f;

    for (int j0 = 0; j0 < NN; j0 += TJ) {
        // issue adj + f2 global loads first (latency overlapped with h stage)
        int a0[16], a1[16];
#pragma unroll
        for (int q = 0; q < 16; ++q) {
            a0[q] = arow[(size_t)q * NN + j0];
            a1[q] = arow[(size_t)q * NN + j0 + 32];
        }
        const float f2x = f2b[j0 + lane];
        const float f2y = f2b[j0 + 32 + lane];

        // stage h tile (64x64 f32)
#pragma unroll
        for (int u = 0; u < 8; ++u)
            ((float4*)h_s)[t + 128 * u] =
                ((const float4*)(hb + (size_t)j0 * FF))[t + 128 * u];

        // scores: p = adj>0 ? exp(lrelu(f1+f2)) : 0
#pragma unroll
        for (int q = 0; q < 16; ++q) {
            const float f1v = f1r[q];
            float xa = (f1v + f2x) * L2E;
            xa = fmaxf(xa, 0.2f * xa);
            float pa = (a0[q] > 0) ? exp2f(xa) : 0.f;
            float xbv = (f1v + f2y) * L2E;
            xbv = fmaxf(xbv, 0.2f * xbv);
            float pb = (a1[q] > 0) ? exp2f(xbv) : 0.f;
            Sacc[q] += pa + pb;
            pT[lane * PTS + 16 * w + q]        = pa;
            pT[(32 + lane) * PTS + 16 * w + q] = pb;
        }
        __syncthreads();   // h_s + pT ready

        // 64x64x64 GEMM accumulate, f32x2
#pragma unroll 8
        for (int k = 0; k < TJ; ++k) {
            const float4 pv = *(const float4*)&pT[k * PTS + ty * 4];
            u64 pd[4];
            PACKDUP(pd[0], pv.x); PACKDUP(pd[1], pv.y);
            PACKDUP(pd[2], pv.z); PACKDUP(pd[3], pv.w);
            ulonglong2 h0 = *(const ulonglong2*)&h_s[k * FF + tx * 8];
            ulonglong2 h1 = *(const ulonglong2*)&h_s[k * FF + tx * 8 + 4];
            u64 hp[4] = {h0.x, h0.y, h1.x, h1.y};
#pragma unroll
            for (int r = 0; r < 4; ++r)
#pragma unroll
                for (int c = 0; c < 4; ++c) FMA2(acc[r][c], pd[r], hp[c], acc[r][c]);
        }
        __syncthreads();   // GEMM done; smem reusable next tile
    }

    // row-sum reduction: butterfly per q, lane q publishes
#pragma unroll
    for (int q = 0; q < 16; ++q) {
        float s = Sacc[q];
#pragma unroll
        for (int o = 1; o < 32; o <<= 1) s += __shfl_xor_sync(0xffffffffu, s, o);
        if (lane == q) Srow[16 * w + q] = s;
    }
    __syncthreads();

    // epilogue: normalize, ELU, store
#pragma unroll
    for (int r = 0; r < 4; ++r) {
        const int row = ty * 4 + r;
        const float inv = 1.0f / Srow[row];
        float o[8];
#pragma unroll
        for (int c = 0; c < 4; ++c) {
            float lo, hi;
            UNPACK2(lo, hi, acc[r][c]);
            o[2 * c]     = lo * inv;
            o[2 * c + 1] = hi * inv;
        }
#pragma unroll
        for (int c = 0; c < 8; ++c) o[c] = o[c] > 0.f ? o[c] : expm1f(o[c]);
        float4* dst = (float4*)(out + ((size_t)b * NN + i0 + row) * FF + tx * 8);
        dst[0] = make_float4(o[0], o[1], o[2], o[3]);
        dst[1] = make_float4(o[4], o[5], o[6], o[7]);
    }
}

// ---------------------------------------------------------------------------
extern "C" void kernel_launch(void* const* d_in, const int* in_sizes, int n_in,
                              void* d_out, int out_size) {
    const float* inp = (const float*)d_in[0];
    const int*   adj = (const int*)d_in[1];
    const float* W   = (const float*)d_in[2];
    const float* a   = (const float*)d_in[3];
    float* out = (float*)d_out;

    cudaFuncSetAttribute(k_hf, cudaFuncAttributeMaxDynamicSharedMemorySize, KHF_SMEM);

    k_hf<<<(BB * NN) / 128, 256, KHF_SMEM>>>(inp, W, a);
    dim3 g(NN / 64, BB);
    k_attn<<<g, 128>>>(adj, out);
}

// round 4
// speedup vs baseline: 1.5766x; 1.4056x over previous
#include <cuda_runtime.h>
#include <math.h>

#define BB 8
#define NN 2048
#define FF 64
#define TJ 64
#define SPLIT 2
#define PTS 66      // pT row stride in floats (264B): 2-way STS, 8B aligned pairs

typedef unsigned long long u64;

__device__ __align__(16) float g_h[BB * NN * FF];
__device__ __align__(16) float g_f1[BB * NN];
__device__ __align__(16) float g_f2[BB * NN];
__device__ __align__(16) float g_part[SPLIT * BB * NN * FF];
__device__ __align__(16) float g_S[SPLIT * BB * NN];

#define FMA2(d, a, b, c) \
    asm("fma.rn.f32x2 %0,%1,%2,%3;" : "=l"(d) : "l"(a), "l"(b), "l"(c))
#define UNPACK2(lo, hi, s) \
    asm("mov.b64 {%0,%1},%2;" : "=f"(lo), "=f"(hi) : "l"(s))
#define PACKDUP(d, x) \
    asm("mov.b64 %0,{%1,%1};" : "=l"(d) : "f"(x))

// ---------------------------------------------------------------------------
// Kernel 1 (proven, ~6us): h = inp@W fused with f1/f2.
// ---------------------------------------------------------------------------
#define PR2 130
#define KHF_SMEM (FF * FF * 4 + FF * PR2 * 8)

__global__ void __launch_bounds__(256) k_hf(const float* __restrict__ inp,
                                            const float* __restrict__ W,
                                            const float* __restrict__ a) {
    extern __shared__ char smem[];
    float*  Ws   = (float*)smem;
    float2* IsT2 = (float2*)(smem + FF * FF * 4);

    const int t    = threadIdx.x;
    const int row0 = blockIdx.x * 128;
    const int tx   = t & 7;
    const int ty   = t >> 3;

#pragma unroll
    for (int q = 0; q < 4; ++q)
        ((float4*)Ws)[t + 256 * q] = ((const float4*)W)[t + 256 * q];

#pragma unroll
    for (int q = 0; q < 8; ++q) {
        int idx = t + 256 * q;
        int r = idx >> 4, k4 = (idx & 15) * 4;
        float4 v = ((const float4*)(inp + (size_t)(row0 + r) * FF))[idx & 15];
        IsT2[(k4 + 0) * PR2 + r] = make_float2(v.x, v.x);
        IsT2[(k4 + 1) * PR2 + r] = make_float2(v.y, v.y);
        IsT2[(k4 + 2) * PR2 + r] = make_float2(v.z, v.z);
        IsT2[(k4 + 3) * PR2 + r] = make_float2(v.w, v.w);
    }
    __syncthreads();

    u64 acc[4][4] = {};
#pragma unroll 8
    for (int k = 0; k < FF; ++k) {
        ulonglong2 p0 = *(const ulonglong2*)&IsT2[k * PR2 + ty * 4];
        ulonglong2 p1 = *(const ulonglong2*)&IsT2[k * PR2 + ty * 4 + 2];
        u64 pd[4] = {p0.x, p0.y, p1.x, p1.y};
        ulonglong2 h0 = *(const ulonglong2*)&Ws[k * FF + tx * 8];
        ulonglong2 h1 = *(const ulonglong2*)&Ws[k * FF + tx * 8 + 4];
        u64 hp[4] = {h0.x, h0.y, h1.x, h1.y};
#pragma unroll
        for (int r = 0; r < 4; ++r)
#pragma unroll
            for (int c = 0; c < 4; ++c) FMA2(acc[r][c], pd[r], hp[c], acc[r][c]);
    }

    float av1[8], av2[8];
#pragma unroll
    for (int c = 0; c < 8; ++c) {
        av1[c] = __ldg(a + tx * 8 + c);
        av2[c] = __ldg(a + 64 + tx * 8 + c);
    }
#pragma unroll
    for (int r = 0; r < 4; ++r) {
        const int row = row0 + ty * 4 + r;
        float hr[8];
#pragma unroll
        for (int c = 0; c < 4; ++c) UNPACK2(hr[2 * c], hr[2 * c + 1], acc[r][c]);
        float4* dst = (float4*)(g_h + (size_t)row * FF + tx * 8);
        dst[0] = make_float4(hr[0], hr[1], hr[2], hr[3]);
        dst[1] = make_float4(hr[4], hr[5], hr[6], hr[7]);
        float s1 = 0.f, s2 = 0.f;
#pragma unroll
        for (int c = 0; c < 8; ++c) { s1 += hr[c] * av1[c]; s2 += hr[c] * av2[c]; }
#pragma unroll
        for (int o = 1; o < 8; o <<= 1) {
            s1 += __shfl_xor_sync(0xffffffffu, s1, o);
            s2 += __shfl_xor_sync(0xffffffffu, s2, o);
        }
        if (tx == 0) { g_f1[row] = s1; g_f2[row] = s2; }
    }
}

// ---------------------------------------------------------------------------
// Kernel 2: fused masked attention + P@h, split over j (partial sums).
// grid = (SPLIT=2, N/64=32, B=8) = 512 CTAs x 256 threads.
// Score phase: warp w owns rows 8w..8w+7, lane = j (coalesced adj).
// GEMM phase: warp tile 16r x 32c (warp_r=w&3, warp_c=w>>2), thread 4r x 4c.
// ---------------------------------------------------------------------------
__global__ void __launch_bounds__(256, 3) k_attn(const int* __restrict__ adj) {
    __shared__ float h_s[TJ * FF];     // [k][c] 16KB
    __shared__ float pT[TJ * PTS];     // [j][r] 16.9KB

    const int t    = threadIdx.x;
    const int w    = t >> 5;
    const int lane = t & 31;
    const int sp   = blockIdx.x;              // j-split 0..1
    const int i0   = blockIdx.y * 64;
    const int b    = blockIdx.z;
    // gemm identity: rows (w&3)*16 + (lane>>3)*4, cols (w>>2)*32 + (lane&7)*4
    const int grow = (w & 3) * 16 + (lane >> 3) * 4;
    const int gcol = (w >> 2) * 32 + (lane & 7) * 4;

    const float* f2b  = g_f2 + (size_t)b * NN;
    const float* hb   = g_h + (size_t)b * NN * FF;
    const int*   arow = adj + ((size_t)b * NN + i0 + 8 * w) * NN + lane;

    float f1r[8];
#pragma unroll
    for (int q = 0; q < 8; ++q) f1r[q] = __ldg(g_f1 + b * NN + i0 + 8 * w + q);

    float Sacc[8];
#pragma unroll
    for (int q = 0; q < 8; ++q) Sacc[q] = 0.f;
    u64 acc[2][4] = {};

    const float L2E = 1.44269504089f;
    const int j_begin = sp * (NN / SPLIT);
    const int j_end   = j_begin + NN / SPLIT;

    for (int j0 = j_begin; j0 < j_end; j0 += TJ) {
        // adj + f2 loads (16 concurrent LDG.32 per thread)
        int a0[8], a1[8];
#pragma unroll
        for (int q = 0; q < 8; ++q) {
            a0[q] = arow[(size_t)q * NN + j0];
            a1[q] = arow[(size_t)q * NN + j0 + 32];
        }
        const float f2x = __ldg(f2b + j0 + lane);
        const float f2y = __ldg(f2b + j0 + 32 + lane);

        // stage h tile (64x64 f32)
#pragma unroll
        for (int u = 0; u < 4; ++u)
            ((float4*)h_s)[t + 256 * u] =
                ((const float4*)(hb + (size_t)j0 * FF))[t + 256 * u];

        // scores
#pragma unroll
        for (int q = 0; q < 8; ++q) {
            const float f1v = f1r[q];
            float xa = (f1v + f2x) * L2E;
            xa = fmaxf(xa, 0.2f * xa);
            float pa = (a0[q] > 0) ? exp2f(xa) : 0.f;
            float xb = (f1v + f2y) * L2E;
            xb = fmaxf(xb, 0.2f * xb);
            float pb = (a1[q] > 0) ? exp2f(xb) : 0.f;
            Sacc[q] += pa + pb;
            pT[lane * PTS + 8 * w + q]        = pa;
            pT[(lane + 32) * PTS + 8 * w + q] = pb;
        }
        __syncthreads();   // h_s + pT ready

        // 64x64x64 GEMM accumulate
#pragma unroll 8
        for (int k = 0; k < TJ; ++k) {
            const u64 pd0 = *(const u64*)&pT[k * PTS + grow];
            const u64 pd1 = *(const u64*)&pT[k * PTS + grow + 2];
            const float4 hv = *(const float4*)&h_s[k * FF + gcol];
            u64 hp[4];
            PACKDUP(hp[0], hv.x); PACKDUP(hp[1], hv.y);
            PACKDUP(hp[2], hv.z); PACKDUP(hp[3], hv.w);
#pragma unroll
            for (int c = 0; c < 4; ++c) {
                FMA2(acc[0][c], pd0, hp[c], acc[0][c]);
                FMA2(acc[1][c], pd1, hp[c], acc[1][c]);
            }
        }
        __syncthreads();   // smem reusable
    }

    // S partial: butterfly over lanes (j), lane q publishes row 8w+q
#pragma unroll
    for (int q = 0; q < 8; ++q) {
        float s = Sacc[q];
#pragma unroll
        for (int o = 1; o < 32; o <<= 1) s += __shfl_xor_sync(0xffffffffu, s, o);
        if (lane == q) g_S[(size_t)sp * BB * NN + b * NN + i0 + 8 * w + q] = s;
    }

    // partial numerators
    float* dst = g_part + ((size_t)sp * BB * NN + b * NN + i0) * FF;
#pragma unroll
    for (int pr = 0; pr < 2; ++pr) {
        float lo[4], hi[4];
#pragma unroll
        for (int c = 0; c < 4; ++c) UNPACK2(lo[c], hi[c], acc[pr][c]);
        *(float4*)(dst + (size_t)(grow + 2 * pr) * FF + gcol) =
            make_float4(lo[0], lo[1], lo[2], lo[3]);
        *(float4*)(dst + (size_t)(grow + 2 * pr + 1) * FF + gcol) =
            make_float4(hi[0], hi[1], hi[2], hi[3]);
    }
}

// ---------------------------------------------------------------------------
// Kernel 3: combine partials, normalize, ELU. 1024 CTAs x 256, 1 float4 each.
// ---------------------------------------------------------------------------
__global__ void __launch_bounds__(256) k_fin(float* __restrict__ out) {
    const int idx = blockIdx.x * 256 + threadIdx.x;   // over 262144 float4
    const int row = idx >> 4;
    const float inv = 1.0f / (g_S[row] + g_S[BB * NN + row]);
    const float4 x0 = ((const float4*)g_part)[idx];
    const float4 x1 = ((const float4*)g_part)[idx + BB * NN * FF / 4];
    float v[4] = {(x0.x + x1.x) * inv, (x0.y + x1.y) * inv,
                  (x0.z + x1.z) * inv, (x0.w + x1.w) * inv};
#pragma unroll
    for (int c = 0; c < 4; ++c) v[c] = v[c] > 0.f ? v[c] : expm1f(v[c]);
    ((float4*)out)[idx] = make_float4(v[0], v[1], v[2], v[3]);
}

// ---------------------------------------------------------------------------
extern "C" void kernel_launch(void* const* d_in, const int* in_sizes, int n_in,
                              void* d_out, int out_size) {
    const float* inp = (const float*)d_in[0];
    const int*   adj = (const int*)d_in[1];
    const float* W   = (const float*)d_in[2];
    const float* a   = (const float*)d_in[3];
    float* out = (float*)d_out;

    cudaFuncSetAttribute(k_hf, cudaFuncAttributeMaxDynamicSharedMemorySize, KHF_SMEM);

    k_hf<<<(BB * NN) / 128, 256, KHF_SMEM>>>(inp, W, a);
    dim3 g(SPLIT, NN / 64, BB);
    k_attn<<<g, 256>>>(adj);
    k_fin<<<(BB * NN * FF) / 4 / 256, 256>>>(out);
}

// round 6
// speedup vs baseline: 2.4489x; 1.5533x over previous
#include <cuda_runtime.h>
#include <cuda_bf16.h>
#include <math.h>
#include <stdint.h>

#define BB 8
#define NN 2048
#define FF 64
#define TJ 128

typedef unsigned long long u64;
typedef unsigned int u32;

// -------------------- device scratch --------------------
__device__ __align__(16) float g_f1[BB * NN];
__device__ __align__(16) float g_f2[BB * NN];
// H^T bf16 planes: [b][n(64)][j(2048)] as u32 pairs (2 bf16 each)
__device__ __align__(16) u32 g_hTh[BB * FF * (NN / 2)];
__device__ __align__(16) u32 g_hTl[BB * FF * (NN / 2)];

// -------------------- PTX helpers --------------------
#define FMA2(d, a, b, c) \
    asm("fma.rn.f32x2 %0,%1,%2,%3;" : "=l"(d) : "l"(a), "l"(b), "l"(c))
#define UNPACK2(lo, hi, s) \
    asm("mov.b64 {%0,%1},%2;" : "=f"(lo), "=f"(hi) : "l"(s))

__device__ __forceinline__ float ex2(float x) {
    float r; asm("ex2.approx.ftz.f32 %0,%1;" : "=f"(r) : "f"(x)); return r;
}
__device__ __forceinline__ u32 smem_u32(const void* p) {
    u32 a;
    asm("{.reg .u64 t; cvta.to.shared.u64 t, %1; cvt.u32.u64 %0, t;}"
        : "=r"(a) : "l"(p));
    return a;
}

#define LDSM4(r0, r1, r2, r3, addr) \
    asm volatile("ldmatrix.sync.aligned.m8n8.x4.shared.b16 {%0,%1,%2,%3}, [%4];" \
                 : "=r"(r0), "=r"(r1), "=r"(r2), "=r"(r3) : "r"(addr))

#define MMA16816(d, a, b0, b1) \
    asm volatile("mma.sync.aligned.m16n8k16.row.col.f32.bf16.bf16.f32 " \
                 "{%0,%1,%2,%3}, {%4,%5,%6,%7}, {%8,%9}, {%0,%1,%2,%3};" \
                 : "+f"((d)[0]), "+f"((d)[1]), "+f"((d)[2]), "+f"((d)[3]) \
                 : "r"((a)[0]), "r"((a)[1]), "r"((a)[2]), "r"((a)[3]), \
                   "r"(b0), "r"(b1))

// bf16 two-term split of a value pair, packed (first elem in low half)
__device__ __forceinline__ void split2(float a, float b, u32& hi, u32& lo) {
    __nv_bfloat16 ah = __float2bfloat16(a), bh = __float2bfloat16(b);
    float ar = a - __bfloat162float(ah);
    float br = b - __bfloat162float(bh);
    __nv_bfloat16 al = __float2bfloat16(ar), bl = __float2bfloat16(br);
    hi = (u32)__bfloat16_as_ushort(ah) | ((u32)__bfloat16_as_ushort(bh) << 16);
    lo = (u32)__bfloat16_as_ushort(al) | ((u32)__bfloat16_as_ushort(bl) << 16);
}

// ---------------------------------------------------------------------------
// Kernel 1: h = inp@W (FMA2), f1/f2, H^T bf16 hi/lo planes (smem transpose).
// 128 CTAs x 512 threads; CTA = 128 h-rows = one (b, j-tile).
// ---------------------------------------------------------------------------
#define PR2 130
#define KHF_SMEM (FF * FF * 4 + FF * PR2 * 8)   // 82944

__global__ void __launch_bounds__(512) k_hf(const float* __restrict__ inp,
                                            const float* __restrict__ W,
                                            const float* __restrict__ a) {
    extern __shared__ char smem[];
    float*  Ws   = (float*)smem;                    // 16KB
    float2* IsT2 = (float2*)(smem + FF * FF * 4);

    const int t    = threadIdx.x;
    const int row0 = blockIdx.x * 128;
    const int tx   = t & 7;          // col group (8 cols)
    const int ty   = t >> 3;         // row pair, 0..63

    ((float4*)Ws)[t]       = ((const float4*)W)[t];
    ((float4*)Ws)[t + 512] = ((const float4*)W)[t + 512];
#pragma unroll
    for (int q = 0; q < 4; ++q) {
        int idx = t + 512 * q;
        int r = idx >> 4, k4 = (idx & 15) * 4;
        float4 v = ((const float4*)(inp + (size_t)(row0 + r) * FF))[idx & 15];
        IsT2[(k4 + 0) * PR2 + r] = make_float2(v.x, v.x);
        IsT2[(k4 + 1) * PR2 + r] = make_float2(v.y, v.y);
        IsT2[(k4 + 2) * PR2 + r] = make_float2(v.z, v.z);
        IsT2[(k4 + 3) * PR2 + r] = make_float2(v.w, v.w);
    }
    __syncthreads();

    u64 acc[2][4] = {};
#pragma unroll 8
    for (int k = 0; k < FF; ++k) {
        ulonglong2 pp = *(const ulonglong2*)&IsT2[k * PR2 + ty * 2];
        u64 pd[2] = {pp.x, pp.y};
        ulonglong2 h0 = *(const ulonglong2*)&Ws[k * FF + tx * 8];
        ulonglong2 h1 = *(const ulonglong2*)&Ws[k * FF + tx * 8 + 4];
        u64 hp[4] = {h0.x, h0.y, h1.x, h1.y};
#pragma unroll
        for (int r = 0; r < 2; ++r)
#pragma unroll
            for (int c = 0; c < 4; ++c) FMA2(acc[r][c], pd[r], hp[c], acc[r][c]);
    }

    float hv[2][8];
#pragma unroll
    for (int r = 0; r < 2; ++r)
#pragma unroll
        for (int c = 0; c < 4; ++c)
            UNPACK2(hv[r][2 * c], hv[r][2 * c + 1], acc[r][c]);

    // f1/f2
    float av1[8], av2[8];
#pragma unroll
    for (int c = 0; c < 8; ++c) {
        av1[c] = __ldg(a + tx * 8 + c);
        av2[c] = __ldg(a + 64 + tx * 8 + c);
    }
#pragma unroll
    for (int r = 0; r < 2; ++r) {
        float s1 = 0.f, s2 = 0.f;
#pragma unroll
        for (int c = 0; c < 8; ++c) { s1 += hv[r][c] * av1[c]; s2 += hv[r][c] * av2[c]; }
#pragma unroll
        for (int o = 1; o < 8; o <<= 1) {
            s1 += __shfl_xor_sync(0xffffffffu, s1, o);
            s2 += __shfl_xor_sync(0xffffffffu, s2, o);
        }
        if (tx == 0) {
            g_f1[row0 + ty * 2 + r] = s1;
            g_f2[row0 + ty * 2 + r] = s2;
        }
    }

    // transpose to bf16 hi/lo planes via smem (reuse IsT2 region)
    __syncthreads();
    u32* trH = (u32*)(smem + 16384);             // [n][68] u32 (64 data + 4 pad)
    u32* trL = trH + 64 * 68;
#pragma unroll
    for (int c = 0; c < 8; ++c) {
        const int n = tx * 8 + c;
        u32 hi, lo;
        split2(hv[0][c], hv[1][c], hi, lo);      // pair (j, j+1), j = 2*ty
        trH[n * 68 + ty] = hi;
        trL[n * 68 + ty] = lo;
    }
    __syncthreads();

    const int b     = row0 >> 11;
    const int jloc0 = row0 & 2047;
    float4* dH = (float4*)g_hTh;
    float4* dL = (float4*)g_hTl;
#pragma unroll
    for (int u = 0; u < 2; ++u) {
        const int idx = t + 512 * u;             // 1024 float4 per plane
        const int n = idx >> 4, c = idx & 15;
        const int gidx = (b * 64 + n) * 256 + (jloc0 >> 3) + c;
        dH[gidx] = *(const float4*)(trH + n * 68 + c * 4);
        dL[gidx] = *(const float4*)(trL + n * 68 + c * 4);
    }
}

// ---------------------------------------------------------------------------
// Kernel 2: attention via mma.sync (bf16 split x3). 256 CTAs x 256 threads.
// CTA = 64 i-rows of one batch; 16 j-tiles of 128.
// Score: warp w owns rows 8w..8w+7, lane -> 4 consecutive j (int4 adj).
// GEMM: warp tile m16 x n32 (m0=(w&3)*16, n0=(w>>2)*32), k = 128 per tile.
// ---------------------------------------------------------------------------
#define PSTRIDE 272                 // bytes per P/HT smem row (136 bf16)
#define SM_PH  0
#define SM_PL  17408
#define SM_HTH 34816
#define SM_HTL 52224
#define SM_SR  69632
#define ATTN_SMEM 69888

__global__ void __launch_bounds__(256) k_attn(const int* __restrict__ adj,
                                              float* __restrict__ out) {
    extern __shared__ char smem[];
    const u32 sb = smem_u32(smem);
    const int t = threadIdx.x;
    const int w = t >> 5, lane = t & 31;
    const int i0 = blockIdx.x * 64;
    const int b  = blockIdx.y;

    // ---- score-phase identity ----
    const int*   abase = adj + ((size_t)(b * NN + i0 + 8 * w)) * NN + lane * 4;
    const float* f2b   = g_f2 + (size_t)b * NN;
    float f1r[8];
#pragma unroll
    for (int q = 0; q < 8; ++q) f1r[q] = __ldg(g_f1 + b * NN + i0 + 8 * w + q);
    float Sacc[8];
#pragma unroll
    for (int q = 0; q < 8; ++q) Sacc[q] = 0.f;

    // ---- gemm-phase identity ----
    const int m0 = (w & 3) * 16;
    const int n0 = (w >> 2) * 32;
    const u32 rowsel = (u32)(lane & 15);
    const u32 colsel = (u32)((lane >> 4) * 16);   // byte offset of k-half
    const u32 aA  = sb + SM_PH  + (m0 + rowsel) * PSTRIDE + colsel;
    const u32 aB0 = sb + SM_HTH + (n0 + rowsel) * PSTRIDE + colsel;
    const u32 aB1 = aB0 + 16 * PSTRIDE;
    float d[4][4] = {};

    const float4* hsH = (const float4*)g_hTh + (size_t)b * 64 * 256;
    const float4* hsL = (const float4*)g_hTl + (size_t)b * 64 * 256;
    const float L2E = 1.44269504089f;

    for (int j0 = 0; j0 < NN; j0 += TJ) {
        __syncthreads();   // previous tile fully consumed

        // ---- stage HT tile (64 n-rows x 128 k, hi+lo) ----
#pragma unroll
        for (int u = 0; u < 4; ++u) {
            const int idx = t + 256 * u;         // 1024 float4 per plane
            const int n = idx >> 4, c = idx & 15;
            const int g = (n << 8) + (j0 >> 3) + c;
            *(float4*)(smem + SM_HTH + n * PSTRIDE + c * 16) = hsH[g];
            *(float4*)(smem + SM_HTL + n * PSTRIDE + c * 16) = hsL[g];
        }

        // ---- scores -> P planes ----
        const float4 f2v = *(const float4*)(f2b + j0 + lane * 4);
#pragma unroll
        for (int q = 0; q < 8; ++q) {
            const int4 av = *(const int4*)(abase + (size_t)q * NN + j0);
            const float f1v = f1r[q];
            float x0 = f1v + f2v.x; x0 = fmaxf(x0, 0.2f * x0);
            float x1 = f1v + f2v.y; x1 = fmaxf(x1, 0.2f * x1);
            float x2 = f1v + f2v.z; x2 = fmaxf(x2, 0.2f * x2);
            float x3 = f1v + f2v.w; x3 = fmaxf(x3, 0.2f * x3);
            const float p0 = (av.x > 0) ? ex2(x0 * L2E) : 0.f;
            const float p1 = (av.y > 0) ? ex2(x1 * L2E) : 0.f;
            const float p2 = (av.z > 0) ? ex2(x2 * L2E) : 0.f;
            const float p3 = (av.w > 0) ? ex2(x3 * L2E) : 0.f;
            Sacc[q] += (p0 + p1) + (p2 + p3);
            u32 h0, l0, h1, l1;
            split2(p0, p1, h0, l0);
            split2(p2, p3, h1, l1);
            char* prow = smem + (8 * w + q) * PSTRIDE + lane * 8;
            *(uint2*)(prow + SM_PH) = make_uint2(h0, h1);
            *(uint2*)(prow + SM_PL) = make_uint2(l0, l1);
        }
        __syncthreads();   // P + HT visible

        // ---- MMA: m16n32 per warp, k=128 in 8 steps ----
#pragma unroll
        for (int kk = 0; kk < 8; ++kk) {
            const u32 off = kk * 32;
            u32 ah[4], al[4], bb[4];
            LDSM4(ah[0], ah[1], ah[2], ah[3], aA + off);
            LDSM4(al[0], al[1], al[2], al[3], aA + SM_PL + off);
            // B hi, n-blocks 0,1
            LDSM4(bb[0], bb[1], bb[2], bb[3], aB0 + off);
            MMA16816(d[0], ah, bb[0], bb[2]);
            MMA16816(d[1], ah, bb[1], bb[3]);
            MMA16816(d[0], al, bb[0], bb[2]);
            MMA16816(d[1], al, bb[1], bb[3]);
            // B hi, n-blocks 2,3
            LDSM4(bb[0], bb[1], bb[2], bb[3], aB1 + off);
            MMA16816(d[2], ah, bb[0], bb[2]);
            MMA16816(d[3], ah, bb[1], bb[3]);
            MMA16816(d[2], al, bb[0], bb[2]);
            MMA16816(d[3], al, bb[1], bb[3]);
            // B lo (only vs A hi)
            LDSM4(bb[0], bb[1], bb[2], bb[3], aB0 + (SM_HTL - SM_HTH) + off);
            MMA16816(d[0], ah, bb[0], bb[2]);
            MMA16816(d[1], ah, bb[1], bb[3]);
            LDSM4(bb[0], bb[1], bb[2], bb[3], aB1 + (SM_HTL - SM_HTH) + off);
            MMA16816(d[2], ah, bb[0], bb[2]);
            MMA16816(d[3], ah, bb[1], bb[3]);
        }
    }

    // ---- softmax denominators ----
    float* Srow = (float*)(smem + SM_SR);
#pragma unroll
    for (int q = 0; q < 8; ++q) {
        float s = Sacc[q];
#pragma unroll
        for (int o = 1; o < 32; o <<= 1) s += __shfl_xor_sync(0xffffffffu, s, o);
        if (lane == q) Srow[8 * w + q] = s;
    }
    __syncthreads();

    // ---- epilogue: normalize, ELU, store ----
    const int r0 = m0 + (lane >> 2);
    const int r1 = r0 + 8;
    const float inv0 = 1.0f / Srow[r0];
    const float inv1 = 1.0f / Srow[r1];
    float* o0 = out + ((size_t)(b * NN + i0 + r0)) * FF + n0 + (lane & 3) * 2;
    float* o1 = out + ((size_t)(b * NN + i0 + r1)) * FF + n0 + (lane & 3) * 2;
#pragma unroll
    for (int nb = 0; nb < 4; ++nb) {
        float v0 = d[nb][0] * inv0, v1 = d[nb][1] * inv0;
        float v2 = d[nb][2] * inv1, v3 = d[nb][3] * inv1;
        v0 = v0 > 0.f ? v0 : expm1f(v0);
        v1 = v1 > 0.f ? v1 : expm1f(v1);
        v2 = v2 > 0.f ? v2 : expm1f(v2);
        v3 = v3 > 0.f ? v3 : expm1f(v3);
        *(float2*)(o0 + nb * 8) = make_float2(v0, v1);
        *(float2*)(o1 + nb * 8) = make_float2(v2, v3);
    }
}

// ---------------------------------------------------------------------------
extern "C" void kernel_launch(void* const* d_in, const int* in_sizes, int n_in,
                              void* d_out, int out_size) {
    const float* inp = (const float*)d_in[0];
    const int*   adj = (const int*)d_in[1];
    const float* W   = (const float*)d_in[2];
    const float* a   = (const float*)d_in[3];
    float* out = (float*)d_out;

    cudaFuncSetAttribute(k_hf, cudaFuncAttributeMaxDynamicSharedMemorySize, KHF_SMEM);
    cudaFuncSetAttribute(k_attn, cudaFuncAttributeMaxDynamicSharedMemorySize, ATTN_SMEM);

    k_hf<<<(BB * NN) / 128, 512, KHF_SMEM>>>(inp, W, a);
    dim3 g(NN / 64, BB);
    k_attn<<<g, 256, ATTN_SMEM>>>(adj, out);
}

// round 7
// speedup vs baseline: 2.8258x; 1.1539x over previous
#include <cuda_runtime.h>
#include <cuda_bf16.h>
#include <math.h>
#include <stdint.h>

#define BB 8
#define NN 2048
#define FF 64
#define TJ 128

typedef unsigned long long u64;
typedef unsigned int u32;

// -------------------- device scratch --------------------
__device__ __align__(16) float g_f1[BB * NN];
__device__ __align__(16) float g_f2[BB * NN];
// H^T bf16 planes: [b][n(64)][j(2048)] as u32 pairs (2 bf16 each)
__device__ __align__(16) u32 g_hTh[BB * FF * (NN / 2)];
__device__ __align__(16) u32 g_hTl[BB * FF * (NN / 2)];
// adj bitmask: word g covers adj ints [g*128, g*128+128); comp c bit L = adj[g*128+4L+c]
__device__ __align__(16) uint4 g_mask[BB * NN * 16];

// -------------------- PTX helpers --------------------
#define FMA2(d, a, b, c) \
    asm("fma.rn.f32x2 %0,%1,%2,%3;" : "=l"(d) : "l"(a), "l"(b), "l"(c))
#define UNPACK2(lo, hi, s) \
    asm("mov.b64 {%0,%1},%2;" : "=f"(lo), "=f"(hi) : "l"(s))

__device__ __forceinline__ float ex2(float x) {
    float r; asm("ex2.approx.ftz.f32 %0,%1;" : "=f"(r) : "f"(x)); return r;
}
__device__ __forceinline__ u32 smem_u32(const void* p) {
    u32 a;
    asm("{.reg .u64 t; cvta.to.shared.u64 t, %1; cvt.u32.u64 %0, t;}"
        : "=r"(a) : "l"(p));
    return a;
}

#define LDSM4(r0, r1, r2, r3, addr) \
    asm volatile("ldmatrix.sync.aligned.m8n8.x4.shared.b16 {%0,%1,%2,%3}, [%4];" \
                 : "=r"(r0), "=r"(r1), "=r"(r2), "=r"(r3) : "r"(addr))

#define MMA16816(d, a, b0, b1) \
    asm volatile("mma.sync.aligned.m16n8k16.row.col.f32.bf16.bf16.f32 " \
                 "{%0,%1,%2,%3}, {%4,%5,%6,%7}, {%8,%9}, {%0,%1,%2,%3};" \
                 : "+f"((d)[0]), "+f"((d)[1]), "+f"((d)[2]), "+f"((d)[3]) \
                 : "r"((a)[0]), "r"((a)[1]), "r"((a)[2]), "r"((a)[3]), \
                   "r"(b0), "r"(b1))

// bf16 two-term split of a pair (first value in low half of each word)
__device__ __forceinline__ void split2(float a, float b, u32& hi, u32& lo) {
    asm("cvt.rn.bf16x2.f32 %0,%1,%2;" : "=r"(hi) : "f"(b), "f"(a));
    float ra = a - __uint_as_float(hi << 16);
    float rb = b - __uint_as_float(hi & 0xFFFF0000u);
    asm("cvt.rn.bf16x2.f32 %0,%1,%2;" : "=r"(lo) : "f"(rb), "f"(ra));
}

// ---------------------------------------------------------------------------
// Kernel 1: blocks [0,128): h = inp@W (FMA2), f1/f2, H^T bf16 hi/lo planes.
//           blocks [128,384): adj -> ballot bitmask (DRAM-stream, hides GEMM).
// 384 CTAs x 512 threads.
// ---------------------------------------------------------------------------
#define PR2 130
#define KHF_SMEM (FF * FF * 4 + FF * PR2 * 8)   // 82944

__global__ void __launch_bounds__(512) k_hf(const float* __restrict__ inp,
                                            const float* __restrict__ W,
                                            const float* __restrict__ a,
                                            const int* __restrict__ adj) {
    const int t = threadIdx.x;

    if (blockIdx.x >= 128) {
        // ---- adj -> bitmask: 4096 warps x 64 uint4 words each ----
        const int gw = (blockIdx.x - 128) * 16 + (t >> 5);
        const int lane = t & 31;
        const int4* src = (const int4*)adj + (size_t)gw * 64 * 32 + lane;
        uint4* dst = g_mask + (size_t)gw * 64;
#pragma unroll 1
        for (int r = 0; r < 8; ++r) {
            int4 v[8];
#pragma unroll
            for (int s = 0; s < 8; ++s) v[s] = src[(r * 8 + s) * 32];
#pragma unroll
            for (int s = 0; s < 8; ++s) {
                uint4 m;
                m.x = __ballot_sync(0xffffffffu, v[s].x > 0);
                m.y = __ballot_sync(0xffffffffu, v[s].y > 0);
                m.z = __ballot_sync(0xffffffffu, v[s].z > 0);
                m.w = __ballot_sync(0xffffffffu, v[s].w > 0);
                if (lane == 0) dst[r * 8 + s] = m;
            }
        }
        return;
    }

    // ---- GEMM + f1/f2 + H^T planes (validated R6 path) ----
    extern __shared__ char smem[];
    float*  Ws   = (float*)smem;
    float2* IsT2 = (float2*)(smem + FF * FF * 4);

    const int row0 = blockIdx.x * 128;
    const int tx   = t & 7;
    const int ty   = t >> 3;

    ((float4*)Ws)[t]       = ((const float4*)W)[t];
    ((float4*)Ws)[t + 512] = ((const float4*)W)[t + 512];
#pragma unroll
    for (int q = 0; q < 4; ++q) {
        int idx = t + 512 * q;
        int r = idx >> 4, k4 = (idx & 15) * 4;
        float4 v = ((const float4*)(inp + (size_t)(row0 + r) * FF))[idx & 15];
        IsT2[(k4 + 0) * PR2 + r] = make_float2(v.x, v.x);
        IsT2[(k4 + 1) * PR2 + r] = make_float2(v.y, v.y);
        IsT2[(k4 + 2) * PR2 + r] = make_float2(v.z, v.z);
        IsT2[(k4 + 3) * PR2 + r] = make_float2(v.w, v.w);
    }
    __syncthreads();

    u64 acc[2][4] = {};
#pragma unroll 8
    for (int k = 0; k < FF; ++k) {
        ulonglong2 pp = *(const ulonglong2*)&IsT2[k * PR2 + ty * 2];
        u64 pd[2] = {pp.x, pp.y};
        ulonglong2 h0 = *(const ulonglong2*)&Ws[k * FF + tx * 8];
        ulonglong2 h1 = *(const ulonglong2*)&Ws[k * FF + tx * 8 + 4];
        u64 hp[4] = {h0.x, h0.y, h1.x, h1.y};
#pragma unroll
        for (int r = 0; r < 2; ++r)
#pragma unroll
            for (int c = 0; c < 4; ++c) FMA2(acc[r][c], pd[r], hp[c], acc[r][c]);
    }

    float hv[2][8];
#pragma unroll
    for (int r = 0; r < 2; ++r)
#pragma unroll
        for (int c = 0; c < 4; ++c)
            UNPACK2(hv[r][2 * c], hv[r][2 * c + 1], acc[r][c]);

    float av1[8], av2[8];
#pragma unroll
    for (int c = 0; c < 8; ++c) {
        av1[c] = __ldg(a + tx * 8 + c);
        av2[c] = __ldg(a + 64 + tx * 8 + c);
    }
#pragma unroll
    for (int r = 0; r < 2; ++r) {
        float s1 = 0.f, s2 = 0.f;
#pragma unroll
        for (int c = 0; c < 8; ++c) { s1 += hv[r][c] * av1[c]; s2 += hv[r][c] * av2[c]; }
#pragma unroll
        for (int o = 1; o < 8; o <<= 1) {
            s1 += __shfl_xor_sync(0xffffffffu, s1, o);
            s2 += __shfl_xor_sync(0xffffffffu, s2, o);
        }
        if (tx == 0) {
            g_f1[row0 + ty * 2 + r] = s1;
            g_f2[row0 + ty * 2 + r] = s2;
        }
    }

    __syncthreads();
    u32* trH = (u32*)(smem + 16384);
    u32* trL = trH + 64 * 68;
#pragma unroll
    for (int c = 0; c < 8; ++c) {
        const int n = tx * 8 + c;
        u32 hi, lo;
        split2(hv[0][c], hv[1][c], hi, lo);
        trH[n * 68 + ty] = hi;
        trL[n * 68 + ty] = lo;
    }
    __syncthreads();

    const int b     = row0 >> 11;
    const int jloc0 = row0 & 2047;
    float4* dH = (float4*)g_hTh;
    float4* dL = (float4*)g_hTl;
#pragma unroll
    for (int u = 0; u < 2; ++u) {
        const int idx = t + 512 * u;
        const int n = idx >> 4, c = idx & 15;
        const int gidx = (b * 64 + n) * 256 + (jloc0 >> 3) + c;
        dH[gidx] = *(const float4*)(trH + n * 68 + c * 4);
        dL[gidx] = *(const float4*)(trL + n * 68 + c * 4);
    }
}

// ---------------------------------------------------------------------------
// Kernel 2: attention via mma.sync (3-term bf16 split). 256 CTAs x 256 thr.
// All score inputs preloaded to smem (masks 16KB, f2*log2e 8KB) -> no DRAM
// in the tile loop except L2-resident HT tiles.
// ---------------------------------------------------------------------------
#define PSTRIDE 272
#define SM_PH  0
#define SM_PL  17408
#define SM_HTH 34816
#define SM_HTL 52224
#define SM_MSK 69632
#define SM_F2  86016
#define SM_SR  94208
#define ATTN_SMEM 94464

__global__ void __launch_bounds__(256, 2) k_attn(float* __restrict__ out) {
    extern __shared__ char smem[];
    const u32 sb = smem_u32(smem);
    const int t = threadIdx.x;
    const int w = t >> 5, lane = t & 31;
    const int i0 = blockIdx.x * 64;
    const int b  = blockIdx.y;

    uint4* msk_s = (uint4*)(smem + SM_MSK);      // [row][tile]
    float* f2s   = (float*)(smem + SM_F2);       // f2 * log2e

    const float L2E = 1.44269504089f;

    // ---- prologue: masks + scaled f2 + f1 ----
    {
        const uint4* gm = g_mask + (size_t)(b * NN + i0) * 16;
#pragma unroll
        for (int u = 0; u < 4; ++u) msk_s[t + 256 * u] = gm[t + 256 * u];
        const float4* f2g = (const float4*)(g_f2 + (size_t)b * NN);
#pragma unroll
        for (int u = 0; u < 2; ++u) {
            float4 v = f2g[t + 256 * u];
            ((float4*)f2s)[t + 256 * u] =
                make_float4(v.x * L2E, v.y * L2E, v.z * L2E, v.w * L2E);
        }
    }

    float f1r[8];
#pragma unroll
    for (int q = 0; q < 8; ++q)
        f1r[q] = __ldg(g_f1 + b * NN + i0 + 8 * w + q) * L2E;
    float Sacc[8];
#pragma unroll
    for (int q = 0; q < 8; ++q) Sacc[q] = 0.f;

    // ---- gemm identity ----
    const int m0 = (w & 3) * 16;
    const int n0 = (w >> 2) * 32;
    const u32 rowsel = (u32)(lane & 15);
    const u32 colsel = (u32)((lane >> 4) * 16);
    const u32 aA  = sb + SM_PH  + (m0 + rowsel) * PSTRIDE + colsel;
    const u32 aB0 = sb + SM_HTH + (n0 + rowsel) * PSTRIDE + colsel;
    const u32 aB1 = aB0 + 16 * PSTRIDE;
    float d[4][4] = {};

    const float4* hsH = (const float4*)g_hTh + (size_t)b * 64 * 256;
    const float4* hsL = (const float4*)g_hTl + (size_t)b * 64 * 256;

    for (int tt = 0; tt < 16; ++tt) {
        __syncthreads();   // previous tile fully consumed (and prologue visible)

        // ---- stage HT tile ----
#pragma unroll
        for (int u = 0; u < 4; ++u) {
            const int idx = t + 256 * u;
            const int n = idx >> 4, c = idx & 15;
            const int g = (n << 8) + (tt << 4) + c;
            *(float4*)(smem + SM_HTH + n * PSTRIDE + c * 16) = hsH[g];
            *(float4*)(smem + SM_HTL + n * PSTRIDE + c * 16) = hsL[g];
        }

        // ---- scores -> P planes (all smem-fed) ----
        const float4 f2v = *(const float4*)(f2s + (tt << 7) + lane * 4);
#pragma unroll
        for (int q = 0; q < 8; ++q) {
            const uint4 m = msk_s[(8 * w + q) * 16 + tt];
            const float f1v = f1r[q];
            float x0 = f1v + f2v.x; x0 = fmaxf(x0, 0.2f * x0);
            float x1 = f1v + f2v.y; x1 = fmaxf(x1, 0.2f * x1);
            float x2 = f1v + f2v.z; x2 = fmaxf(x2, 0.2f * x2);
            float x3 = f1v + f2v.w; x3 = fmaxf(x3, 0.2f * x3);
            const float p0 = ((m.x >> lane) & 1u) ? ex2(x0) : 0.f;
            const float p1 = ((m.y >> lane) & 1u) ? ex2(x1) : 0.f;
            const float p2 = ((m.z >> lane) & 1u) ? ex2(x2) : 0.f;
            const float p3 = ((m.w >> lane) & 1u) ? ex2(x3) : 0.f;
            Sacc[q] += (p0 + p1) + (p2 + p3);
            u32 h0, l0, h1, l1;
            split2(p0, p1, h0, l0);
            split2(p2, p3, h1, l1);
            char* prow = smem + (8 * w + q) * PSTRIDE + lane * 8;
            *(uint2*)(prow + SM_PH) = make_uint2(h0, h1);
            *(uint2*)(prow + SM_PL) = make_uint2(l0, l1);
        }
        __syncthreads();   // P + HT visible

        // ---- MMA: m16n32 per warp, k=128, 3 split terms ----
#pragma unroll
        for (int kk = 0; kk < 8; ++kk) {
            const u32 off = kk * 32;
            u32 ah[4], al[4], bb[4];
            LDSM4(ah[0], ah[1], ah[2], ah[3], aA + off);
            LDSM4(al[0], al[1], al[2], al[3], aA + (SM_PL - SM_PH) + off);
            LDSM4(bb[0], bb[1], bb[2], bb[3], aB0 + off);
            MMA16816(d[0], ah, bb[0], bb[2]);
            MMA16816(d[1], ah, bb[1], bb[3]);
            MMA16816(d[0], al, bb[0], bb[2]);
            MMA16816(d[1], al, bb[1], bb[3]);
            LDSM4(bb[0], bb[1], bb[2], bb[3], aB1 + off);
            MMA16816(d[2], ah, bb[0], bb[2]);
            MMA16816(d[3], ah, bb[1], bb[3]);
            MMA16816(d[2], al, bb[0], bb[2]);
            MMA16816(d[3], al, bb[1], bb[3]);
            LDSM4(bb[0], bb[1], bb[2], bb[3], aB0 + (SM_HTL - SM_HTH) + off);
            MMA16816(d[0], ah, bb[0], bb[2]);
            MMA16816(d[1], ah, bb[1], bb[3]);
            LDSM4(bb[0], bb[1], bb[2], bb[3], aB1 + (SM_HTL - SM_HTH) + off);
            MMA16816(d[2], ah, bb[0], bb[2]);
            MMA16816(d[3], ah, bb[1], bb[3]);
        }
    }

    // ---- softmax denominators ----
    float* Srow = (float*)(smem + SM_SR);
#pragma unroll
    for (int q = 0; q < 8; ++q) {
        float s = Sacc[q];
#pragma unroll
        for (int o = 1; o < 32; o <<= 1) s += __shfl_xor_sync(0xffffffffu, s, o);
        if (lane == q) Srow[8 * w + q] = s;
    }
    __syncthreads();

    // ---- epilogue ----
    const int r0 = m0 + (lane >> 2);
    const int r1 = r0 + 8;
    const float inv0 = 1.0f / Srow[r0];
    const float inv1 = 1.0f / Srow[r1];
    float* o0 = out + ((size_t)(b * NN + i0 + r0)) * FF + n0 + (lane & 3) * 2;
    float* o1 = out + ((size_t)(b * NN + i0 + r1)) * FF + n0 + (lane & 3) * 2;
#pragma unroll
    for (int nb = 0; nb < 4; ++nb) {
        float v0 = d[nb][0] * inv0, v1 = d[nb][1] * inv0;
        float v2 = d[nb][2] * inv1, v3 = d[nb][3] * inv1;
        v0 = v0 > 0.f ? v0 : expm1f(v0);
        v1 = v1 > 0.f ? v1 : expm1f(v1);
        v2 = v2 > 0.f ? v2 : expm1f(v2);
        v3 = v3 > 0.f ? v3 : expm1f(v3);
        *(float2*)(o0 + nb * 8) = make_float2(v0, v1);
        *(float2*)(o1 + nb * 8) = make_float2(v2, v3);
    }
}

// ---------------------------------------------------------------------------
extern "C" void kernel_launch(void* const* d_in, const int* in_sizes, int n_in,
                              void* d_out, int out_size) {
    const float* inp = (const float*)d_in[0];
    const int*   adj = (const int*)d_in[1];
    const float* W   = (const float*)d_in[2];
    const float* a   = (const float*)d_in[3];
    float* out = (float*)d_out;

    cudaFuncSetAttribute(k_hf, cudaFuncAttributeMaxDynamicSharedMemorySize, KHF_SMEM);
    cudaFuncSetAttribute(k_attn, cudaFuncAttributeMaxDynamicSharedMemorySize, ATTN_SMEM);

    k_hf<<<128 + 256, 512, KHF_SMEM>>>(inp, W, a, adj);
    dim3 g(NN / 64, BB);
    k_attn<<<g, 256, ATTN_SMEM>>>(out);
}

// round 8
// speedup vs baseline: 2.9150x; 1.0316x over previous
#include <cuda_runtime.h>
#include <cuda_bf16.h>
#include <math.h>
#include <stdint.h>

#define BB 8
#define NN 2048
#define FF 64
#define TJ 128

typedef unsigned long long u64;
typedef unsigned int u32;

// -------------------- device scratch --------------------
__device__ __align__(16) float g_f1[BB * NN];     // prescaled by log2(e)
__device__ __align__(16) float g_f2[BB * NN];     // prescaled by log2(e)
__device__ __align__(16) u32 g_hTh[BB * FF * (NN / 2)];
__device__ __align__(16) u32 g_hTl[BB * FF * (NN / 2)];
__device__ __align__(16) uint4 g_mask[BB * NN * 16];

// -------------------- PTX helpers --------------------
#define FMA2(d, a, b, c) \
    asm("fma.rn.f32x2 %0,%1,%2,%3;" : "=l"(d) : "l"(a), "l"(b), "l"(c))
#define UNPACK2(lo, hi, s) \
    asm("mov.b64 {%0,%1},%2;" : "=f"(lo), "=f"(hi) : "l"(s))

__device__ __forceinline__ float ex2(float x) {
    float r; asm("ex2.approx.ftz.f32 %0,%1;" : "=f"(r) : "f"(x)); return r;
}
__device__ __forceinline__ u32 smem_u32(const void* p) {
    u32 a;
    asm("{.reg .u64 t; cvta.to.shared.u64 t, %1; cvt.u32.u64 %0, t;}"
        : "=r"(a) : "l"(p));
    return a;
}

#define CPASYNC16(saddr, gptr) \
    asm volatile("cp.async.ca.shared.global [%0], [%1], 16;" \
                 :: "r"(saddr), "l"(gptr) : "memory")
#define CPCOMMIT() asm volatile("cp.async.commit_group;" ::: "memory")
#define CPWAIT0()  asm volatile("cp.async.wait_group 0;" ::: "memory")

#define LDSM4(r0, r1, r2, r3, addr) \
    asm volatile("ldmatrix.sync.aligned.m8n8.x4.shared.b16 {%0,%1,%2,%3}, [%4];" \
                 : "=r"(r0), "=r"(r1), "=r"(r2), "=r"(r3) : "r"(addr))

#define MMA16816(d, a, b0, b1) \
    asm volatile("mma.sync.aligned.m16n8k16.row.col.f32.bf16.bf16.f32 " \
                 "{%0,%1,%2,%3}, {%4,%5,%6,%7}, {%8,%9}, {%0,%1,%2,%3};" \
                 : "+f"((d)[0]), "+f"((d)[1]), "+f"((d)[2]), "+f"((d)[3]) \
                 : "r"((a)[0]), "r"((a)[1]), "r"((a)[2]), "r"((a)[3]), \
                   "r"(b0), "r"(b1))

__device__ __forceinline__ void split2(float a, float b, u32& hi, u32& lo) {
    asm("cvt.rn.bf16x2.f32 %0,%1,%2;" : "=r"(hi) : "f"(b), "f"(a));
    float ra = a - __uint_as_float(hi << 16);
    float rb = b - __uint_as_float(hi & 0xFFFF0000u);
    asm("cvt.rn.bf16x2.f32 %0,%1,%2;" : "=r"(lo) : "f"(rb), "f"(ra));
}

// ---------------------------------------------------------------------------
// Kernel 1: blocks [0,128): h = inp@W, f1/f2 (prescaled), H^T bf16 planes.
//           blocks [128,384): adj -> ballot bitmask.
// ---------------------------------------------------------------------------
#define PR2 130
#define KHF_SMEM (FF * FF * 4 + FF * PR2 * 8)

__global__ void __launch_bounds__(512) k_hf(const float* __restrict__ inp,
                                            const float* __restrict__ W,
                                            const float* __restrict__ a,
                                            const int* __restrict__ adj) {
    const int t = threadIdx.x;
    const float L2E = 1.44269504089f;

    if (blockIdx.x >= 128) {
        const int gw = (blockIdx.x - 128) * 16 + (t >> 5);
        const int lane = t & 31;
        const int4* src = (const int4*)adj + (size_t)gw * 64 * 32 + lane;
        uint4* dst = g_mask + (size_t)gw * 64;
#pragma unroll 1
        for (int r = 0; r < 8; ++r) {
            int4 v[8];
#pragma unroll
            for (int s = 0; s < 8; ++s) v[s] = src[(r * 8 + s) * 32];
#pragma unroll
            for (int s = 0; s < 8; ++s) {
                uint4 m;
                m.x = __ballot_sync(0xffffffffu, v[s].x > 0);
                m.y = __ballot_sync(0xffffffffu, v[s].y > 0);
                m.z = __ballot_sync(0xffffffffu, v[s].z > 0);
                m.w = __ballot_sync(0xffffffffu, v[s].w > 0);
                if (lane == 0) dst[r * 8 + s] = m;
            }
        }
        return;
    }

    extern __shared__ char smem[];
    float*  Ws   = (float*)smem;
    float2* IsT2 = (float2*)(smem + FF * FF * 4);

    const int row0 = blockIdx.x * 128;
    const int tx   = t & 7;
    const int ty   = t >> 3;

    ((float4*)Ws)[t]       = ((const float4*)W)[t];
    ((float4*)Ws)[t + 512] = ((const float4*)W)[t + 512];
#pragma unroll
    for (int q = 0; q < 4; ++q) {
        int idx = t + 512 * q;
        int r = idx >> 4, k4 = (idx & 15) * 4;
        float4 v = ((const float4*)(inp + (size_t)(row0 + r) * FF))[idx & 15];
        IsT2[(k4 + 0) * PR2 + r] = make_float2(v.x, v.x);
        IsT2[(k4 + 1) * PR2 + r] = make_float2(v.y, v.y);
        IsT2[(k4 + 2) * PR2 + r] = make_float2(v.z, v.z);
        IsT2[(k4 + 3) * PR2 + r] = make_float2(v.w, v.w);
    }
    __syncthreads();

    u64 acc[2][4] = {};
#pragma unroll 8
    for (int k = 0; k < FF; ++k) {
        ulonglong2 pp = *(const ulonglong2*)&IsT2[k * PR2 + ty * 2];
        u64 pd[2] = {pp.x, pp.y};
        ulonglong2 h0 = *(const ulonglong2*)&Ws[k * FF + tx * 8];
        ulonglong2 h1 = *(const ulonglong2*)&Ws[k * FF + tx * 8 + 4];
        u64 hp[4] = {h0.x, h0.y, h1.x, h1.y};
#pragma unroll
        for (int r = 0; r < 2; ++r)
#pragma unroll
            for (int c = 0; c < 4; ++c) FMA2(acc[r][c], pd[r], hp[c], acc[r][c]);
    }

    float hv[2][8];
#pragma unroll
    for (int r = 0; r < 2; ++r)
#pragma unroll
        for (int c = 0; c < 4; ++c)
            UNPACK2(hv[r][2 * c], hv[r][2 * c + 1], acc[r][c]);

    float av1[8], av2[8];
#pragma unroll
    for (int c = 0; c < 8; ++c) {
        av1[c] = __ldg(a + tx * 8 + c);
        av2[c] = __ldg(a + 64 + tx * 8 + c);
    }
#pragma unroll
    for (int r = 0; r < 2; ++r) {
        float s1 = 0.f, s2 = 0.f;
#pragma unroll
        for (int c = 0; c < 8; ++c) { s1 += hv[r][c] * av1[c]; s2 += hv[r][c] * av2[c]; }
#pragma unroll
        for (int o = 1; o < 8; o <<= 1) {
            s1 += __shfl_xor_sync(0xffffffffu, s1, o);
            s2 += __shfl_xor_sync(0xffffffffu, s2, o);
        }
        if (tx == 0) {
            g_f1[row0 + ty * 2 + r] = s1 * L2E;
            g_f2[row0 + ty * 2 + r] = s2 * L2E;
        }
    }

    __syncthreads();
    u32* trH = (u32*)(smem + 16384);
    u32* trL = trH + 64 * 68;
#pragma unroll
    for (int c = 0; c < 8; ++c) {
        const int n = tx * 8 + c;
        u32 hi, lo;
        split2(hv[0][c], hv[1][c], hi, lo);
        trH[n * 68 + ty] = hi;
        trL[n * 68 + ty] = lo;
    }
    __syncthreads();

    const int b     = row0 >> 11;
    const int jloc0 = row0 & 2047;
    float4* dH = (float4*)g_hTh;
    float4* dL = (float4*)g_hTl;
#pragma unroll
    for (int u = 0; u < 2; ++u) {
        const int idx = t + 512 * u;
        const int n = idx >> 4, c = idx & 15;
        const int gidx = (b * 64 + n) * 256 + (jloc0 >> 3) + c;
        dH[gidx] = *(const float4*)(trH + n * 68 + c * 4);
        dL[gidx] = *(const float4*)(trL + n * 68 + c * 4);
    }
}

// ---------------------------------------------------------------------------
// Kernel 2: attention via mma.sync (3-term bf16 split). 256 CTAs x 256 thr.
// cp.async HT staging (latency hidden under scores), round-robin MMA order.
// ---------------------------------------------------------------------------
#define PSTRIDE 272
#define SM_PH  0
#define SM_PL  17408
#define SM_HTH 34816
#define SM_HTL 52224
#define SM_MSK 69632
#define SM_F2  86016
#define SM_SR  94208
#define ATTN_SMEM 94464

__global__ void __launch_bounds__(256, 2) k_attn(float* __restrict__ out) {
    extern __shared__ char smem[];
    const u32 sb = smem_u32(smem);
    const int t = threadIdx.x;
    const int w = t >> 5, lane = t & 31;
    const int i0 = blockIdx.x * 64;
    const int b  = blockIdx.y;

    uint4* msk_s = (uint4*)(smem + SM_MSK);
    float* f2s   = (float*)(smem + SM_F2);

    // ---- prologue: masks + f2 (already log2e-scaled) ----
    {
        const uint4* gm = g_mask + (size_t)(b * NN + i0) * 16;
#pragma unroll
        for (int u = 0; u < 4; ++u) msk_s[t + 256 * u] = gm[t + 256 * u];
        const float4* f2g = (const float4*)(g_f2 + (size_t)b * NN);
#pragma unroll
        for (int u = 0; u < 2; ++u) ((float4*)f2s)[t + 256 * u] = f2g[t + 256 * u];
    }

    float f1r[8];
#pragma unroll
    for (int q = 0; q < 8; ++q) f1r[q] = __ldg(g_f1 + b * NN + i0 + 8 * w + q);
    float Sacc[8];
#pragma unroll
    for (int q = 0; q < 8; ++q) Sacc[q] = 0.f;

    const int m0 = (w & 3) * 16;
    const int n0 = (w >> 2) * 32;
    const u32 rowsel = (u32)(lane & 15);
    const u32 colsel = (u32)((lane >> 4) * 16);
    const u32 aA  = sb + SM_PH  + (m0 + rowsel) * PSTRIDE + colsel;
    const u32 aB0 = sb + SM_HTH + (n0 + rowsel) * PSTRIDE + colsel;
    const u32 aB1 = aB0 + 16 * PSTRIDE;
    float d[4][4] = {};

    const float4* hsH = (const float4*)g_hTh + (size_t)b * 64 * 256;
    const float4* hsL = (const float4*)g_hTl + (size_t)b * 64 * 256;

    // cp.async staging identity (per thread: 4 idx slots x 2 planes)
    const int stg_n = t >> 4, stg_c = t & 15;

    for (int tt = 0; tt < 16; ++tt) {
        __syncthreads();   // all reads of previous tile done

        // ---- HT tile via cp.async (completes under score phase) ----
#pragma unroll
        for (int u = 0; u < 4; ++u) {
            const int n = stg_n + 16 * u;
            const int g = (n << 8) + (tt << 4) + stg_c;
            const u32 so = (u32)(n * PSTRIDE + stg_c * 16);
            CPASYNC16(sb + SM_HTH + so, hsH + g);
            CPASYNC16(sb + SM_HTL + so, hsL + g);
        }
        CPCOMMIT();

        // ---- scores -> P planes ----
        const float4 f2v = *(const float4*)(f2s + (tt << 7) + lane * 4);
#pragma unroll
        for (int q = 0; q < 8; ++q) {
            const uint4 m = msk_s[(8 * w + q) * 16 + tt];
            const float f1v = f1r[q];
            float x0 = f1v + f2v.x; x0 = fmaxf(x0, 0.2f * x0);
            float x1 = f1v + f2v.y; x1 = fmaxf(x1, 0.2f * x1);
            float x2 = f1v + f2v.z; x2 = fmaxf(x2, 0.2f * x2);
            float x3 = f1v + f2v.w; x3 = fmaxf(x3, 0.2f * x3);
            const float p0 = ((m.x >> lane) & 1u) ? ex2(x0) : 0.f;
            const float p1 = ((m.y >> lane) & 1u) ? ex2(x1) : 0.f;
            const float p2 = ((m.z >> lane) & 1u) ? ex2(x2) : 0.f;
            const float p3 = ((m.w >> lane) & 1u) ? ex2(x3) : 0.f;
            Sacc[q] += (p0 + p1) + (p2 + p3);
            u32 h0, l0, h1, l1;
            split2(p0, p1, h0, l0);
            split2(p2, p3, h1, l1);
            char* prow = smem + (8 * w + q) * PSTRIDE + lane * 8;
            *(uint2*)(prow + SM_PH) = make_uint2(h0, h1);
            *(uint2*)(prow + SM_PL) = make_uint2(l0, l1);
        }
        CPWAIT0();
        __syncthreads();   // P + HT visible

        // ---- MMA: all quads loaded, round-robin accumulators ----
#pragma unroll
        for (int kk = 0; kk < 8; ++kk) {
            const u32 off = kk * 32;
            u32 ah[4], al[4], bh0[4], bh1[4], bl0[4], bl1[4];
            LDSM4(ah[0], ah[1], ah[2], ah[3], aA + off);
            LDSM4(al[0], al[1], al[2], al[3], aA + (SM_PL - SM_PH) + off);
            LDSM4(bh0[0], bh0[1], bh0[2], bh0[3], aB0 + off);
            LDSM4(bh1[0], bh1[1], bh1[2], bh1[3], aB1 + off);
            LDSM4(bl0[0], bl0[1], bl0[2], bl0[3], aB0 + (SM_HTL - SM_HTH) + off);
            LDSM4(bl1[0], bl1[1], bl1[2], bl1[3], aB1 + (SM_HTL - SM_HTH) + off);
            MMA16816(d[0], ah, bh0[0], bh0[2]);
            MMA16816(d[1], ah, bh0[1], bh0[3]);
            MMA16816(d[2], ah, bh1[0], bh1[2]);
            MMA16816(d[3], ah, bh1[1], bh1[3]);
            MMA16816(d[0], al, bh0[0], bh0[2]);
            MMA16816(d[1], al, bh0[1], bh0[3]);
            MMA16816(d[2], al, bh1[0], bh1[2]);
            MMA16816(d[3], al, bh1[1], bh1[3]);
            MMA16816(d[0], ah, bl0[0], bl0[2]);
            MMA16816(d[1], ah, bl0[1], bl0[3]);
            MMA16816(d[2], ah, bl1[0], bl1[2]);
            MMA16816(d[3], ah, bl1[1], bl1[3]);
        }
    }

    // ---- softmax denominators ----
    float* Srow = (float*)(smem + SM_SR);
#pragma unroll
    for (int q = 0; q < 8; ++q) {
        float s = Sacc[q];
#pragma unroll
        for (int o = 1; o < 32; o <<= 1) s += __shfl_xor_sync(0xffffffffu, s, o);
        if (lane == q) Srow[8 * w + q] = s;
    }
    __syncthreads();

    // ---- epilogue ----
    const int r0 = m0 + (lane >> 2);
    const int r1 = r0 + 8;
    const float inv0 = 1.0f / Srow[r0];
    const float inv1 = 1.0f / Srow[r1];
    float* o0 = out + ((size_t)(b * NN + i0 + r0)) * FF + n0 + (lane & 3) * 2;
    float* o1 = out + ((size_t)(b * NN + i0 + r1)) * FF + n0 + (lane & 3) * 2;
#pragma unroll
    for (int nb = 0; nb < 4; ++nb) {
        float v0 = d[nb][0] * inv0, v1 = d[nb][1] * inv0;
        float v2 = d[nb][2] * inv1, v3 = d[nb][3] * inv1;
        v0 = v0 > 0.f ? v0 : expm1f(v0);
        v1 = v1 > 0.f ? v1 : expm1f(v1);
        v2 = v2 > 0.f ? v2 : expm1f(v2);
        v3 = v3 > 0.f ? v3 : expm1f(v3);
        *(float2*)(o0 + nb * 8) = make_float2(v0, v1);
        *(float2*)(o1 + nb * 8) = make_float2(v2, v3);
    }
}

// ---------------------------------------------------------------------------
extern "C" void kernel_launch(void* const* d_in, const int* in_sizes, int n_in,
                              void* d_out, int out_size) {
    const float* inp = (const float*)d_in[0];
    const int*   adj = (const int*)d_in[1];
    const float* W   = (const float*)d_in[2];
    const float* a   = (const float*)d_in[3];
    float* out = (float*)d_out;

    cudaFuncSetAttribute(k_hf, cudaFuncAttributeMaxDynamicSharedMemorySize, KHF_SMEM);
    cudaFuncSetAttribute(k_attn, cudaFuncAttributeMaxDynamicSharedMemorySize, ATTN_SMEM);

    k_hf<<<128 + 256, 512, KHF_SMEM>>>(inp, W, a, adj);
    dim3 g(NN / 64, BB);
    k_attn<<<g, 256, ATTN_SMEM>>>(out);
}